// round 8
// baseline (speedup 1.0000x reference)
#include <cuda_runtime.h>
#include <cstdint>

#define N_WL 262144

// Persistent scratch (no allocations allowed)
__device__ float g_m2[64];
__device__ float g_h[32];

__device__ const float LNU0[10]  = {254.f, 280.f, 310.f, 940.f, 1130.f, 1380.f, 1400.f, 1600.f, 2000.f, 2700.f};
__device__ const float LSTR[10]  = {1.15e-17f, 5e-18f, 1.9e-19f, 2.5e-23f, 8.2e-24f, 1.8e-22f, 3.5e-25f, 7.8e-26f, 4.2e-24f, 1.2e-24f};
__device__ const float LWID[10]  = {2.0f, 3.0f, 2.5f, 3.0f, 2.5f, 4.0f, 3.0f, 2.5f, 4.0f, 3.5f};
__device__ const float LTE[10]   = {0.05f, 0.04f, 0.03f, 0.4f, 0.35f, 0.45f, 0.5f, 0.48f, 0.52f, 0.49f};
__device__ const float LMASS[10] = {48.f, 48.f, 48.f, 18.f, 18.f, 18.f, 44.f, 44.f, 44.f, 44.f};

// Voigt profile contribution for one line (prep kernel only).
__device__ __forceinline__ float voigt_line(float wl, float4 L) {
    float x  = (wl - L.x) * L.y;
    float y  = L.z;
    float ax = fabsf(x);
    float s  = ax + y;
    float w;
    if (s >= 15.0f) {
        float t2r = y * y - x * x;
        float t2i = -2.0f * x * y;
        float dr  = 0.5f + t2r;
        float di  = t2i;
        float nr  = 0.5641896f * y;
        float ni  = 0.5641896f * (-x);
        w = (nr * dr + ni * di) / (dr * dr + di * di);
    } else if (ax >= 5.5f) {
        float tr = y, ti = -x;
        float ur = y * y - x * x;
        float ui = -2.0f * x * y;
        float ar = 1.410474f + 0.5641896f * ur;
        float ai = 0.5641896f * ui;
        float nr = tr * ar - ti * ai;
        float ni = tr * ai + ti * ar;
        float u2r = ur * ur - ui * ui;
        float u2i = 2.0f * ur * ui;
        float dr = 0.75f + 3.0f * ur + u2r;
        float di = 3.0f * ui + u2i;
        w = (nr * dr + ni * di) / (dr * dr + di * di);
    } else {
        float xx = x * x;
        w = expf(-xx) * cosf(2.0f * x * y) * 0.5641896f
          + (2.0f * y / 3.14159265358979f) * sinf(xx) / (xx + y * y + 1e-10f);
    }
    return L.w * w;
}

__device__ __forceinline__ float softplus_f(float z) {
    return fmaxf(z, 0.0f) + log1pf(expf(-fabsf(z)));
}
__device__ __forceinline__ float silu_f(float z) {
    return z / (1.0f + expf(-z));
}
__device__ __forceinline__ float tanh_approx(float z) {
    float r;
    asm("tanh.approx.f32 %0, %1;" : "=f"(r) : "f"(z));
    return r;
}

// ---- bulk-async (TMA engine) helpers ----
__device__ __forceinline__ uint32_t smem_u32(const void* p) {
    uint32_t a;
    asm("{ .reg .u64 t; cvta.to.shared.u64 t, %1; cvt.u32.u64 %0, t; }" : "=r"(a) : "l"(p));
    return a;
}
__device__ __forceinline__ void mbar_init(uint32_t mbar, uint32_t cnt) {
    asm volatile("mbarrier.init.shared.b64 [%0], %1;" :: "r"(mbar), "r"(cnt) : "memory");
}
__device__ __forceinline__ void mbar_expect_tx(uint32_t mbar, uint32_t bytes) {
    asm volatile("mbarrier.arrive.expect_tx.shared.b64 _, [%0], %1;" :: "r"(mbar), "r"(bytes) : "memory");
}
__device__ __forceinline__ void bulk_cp(uint32_t dst_smem, const void* src, uint32_t bytes, uint32_t mbar) {
    asm volatile(
        "cp.async.bulk.shared::cluster.global.mbarrier::complete_tx::bytes [%0], [%1], %2, [%3];"
        :: "r"(dst_smem), "l"(src), "r"(bytes), "r"(mbar) : "memory");
}
__device__ __forceinline__ void mbar_wait(uint32_t mbar) {
    asm volatile(
        "{\n\t"
        ".reg .pred P;\n\t"
        "W%=:\n\t"
        "mbarrier.try_wait.parity.acquire.cta.shared::cta.b64 P, [%0], 0, 0x989680;\n\t"
        "@P bra D%=;\n\t"
        "bra W%=;\n\t"
        "D%=:\n\t"
        "}"
        :: "r"(mbar) : "memory");
}

// SMEM layout (bytes)
#define SM_W3   0        // 64 rows x 1024B
#define SM_CW   65536    // 32 rows x 1024B
#define SM_MB3  98304    // 1024B
#define SM_CB2  99328    // 1024B
#define SM_M2   100352   // 64 floats
#define SM_H    100608   // 32 floats
#define SM_MBAR 100736   // 4 x 8B mbarriers
#define SMEM_TOTAL 100864

// ---------------------------------------------------------------------------
// Kernel A: tiny prep — line coefficients, h[32], cross[:8], m2[64]
// ---------------------------------------------------------------------------
__global__ void prep_kernel(
    const float* __restrict__ wl,
    const float* __restrict__ Tp,  const float* __restrict__ Pp,
    const float* __restrict__ o3p, const float* __restrict__ h2op, const float* __restrict__ co2p,
    const float* __restrict__ mix_w1,  const float* __restrict__ mix_b1,
    const float* __restrict__ mix_w2,  const float* __restrict__ mix_b2,
    const float* __restrict__ cont_w1, const float* __restrict__ cont_b1,
    const float* __restrict__ cont_w2, const float* __restrict__ cont_b2)
{
    __shared__ float4 s_line[10];
    __shared__ float  s_h[32];
    __shared__ float  s_feat[10];
    __shared__ float  s_m1[64];

    const int t = threadIdx.x;   // 64 threads
    const float T = Tp[0];
    const float P = Pp[0];

    if (t < 10) {
        float conc = (t < 3) ? o3p[0] : ((t < 6) ? h2op[0] : co2p[0]);
        float nu0  = LNU0[t];
        float sT   = LSTR[t] * powf(273.15f / (T + 1e-12f), LTE[t]);
        float gL   = LWID[t] * (P / 101325.0f) * sqrtf(273.15f / (T + 1e-12f));
        float g    = 2.0f * 1.380649e-23f * T;
        g *= 6.02214076e23f;
        g /= (LMASS[t] + 1e-12f);
        float gD    = nu0 / 2.99792458e8f * sqrtf(g);
        float sigma = gD / 1.1774100226f;
        float inv_s = 1.0f / (sigma + 1e-12f);
        float y     = gL * inv_s;
        float amp   = conc * sT / (sigma * 1.7724538509f + 1e-12f);
        s_line[t] = make_float4(nu0, inv_s, y, amp);
    }
    if (t < 32) {
        float f0 = T / 273.15f;
        float f1 = P / 101325.0f;
        float f2 = h2op[0];
        float z = cont_b1[t]
                + f0 * cont_w1[t]
                + f1 * cont_w1[32 + t]
                + f2 * cont_w1[64 + t]
                +      cont_w1[96 + t];    // feat[3] = 1, feat[4] = 0
        float h = silu_f(z);
        s_h[t] = h;
        g_h[t] = h;
    }
    if (t == 0) {
        s_feat[0] = T / 273.15f;
        s_feat[1] = P / 101325.0f;
    }
    __syncthreads();

    if (t < 8) {
        float w = wl[t];
        float cross = 0.0f;
        #pragma unroll
        for (int l = 0; l < 10; l++) cross += voigt_line(w, s_line[l]);
        float z = cont_b2[t];
        #pragma unroll
        for (int j = 0; j < 32; j++) z += s_h[j] * cont_w2[j * N_WL + t];
        s_feat[2 + t] = cross + softplus_f(z);
    }
    __syncthreads();

    {
        float z = mix_b1[t];
        #pragma unroll
        for (int k = 0; k < 10; k++) z += s_feat[k] * mix_w1[k * 64 + t];
        s_m1[t] = silu_f(z);
    }
    __syncthreads();

    {
        float z = mix_b2[t];
        #pragma unroll
        for (int k = 0; k < 64; k++) z += s_m1[k] * mix_w2[k * 64 + t];
        g_m2[t] = silu_f(z);
    }
}

// ---------------------------------------------------------------------------
// Kernel B: bulk-async (TMA-engine) staged version.
// Each CTA owns 256 columns; 98 x 1KB bulk copies into smem in 4 mbarrier
// groups; compute on group g overlaps copies of groups g+1..3.
// ---------------------------------------------------------------------------
__global__ void __launch_bounds__(256) main_kernel(
    const float* __restrict__ mix_w3,  const float* __restrict__ mix_b3,
    const float* __restrict__ cont_w2, const float* __restrict__ cont_b2,
    float* __restrict__ out)
{
    extern __shared__ char sm[];
    const int t = threadIdx.x;
    const int c0 = blockIdx.x * 256;            // first column of this CTA

    float* s_w3 = (float*)(sm + SM_W3);
    float* s_cw = (float*)(sm + SM_CW);
    float* s_b3 = (float*)(sm + SM_MB3);
    float* s_cb = (float*)(sm + SM_CB2);
    float* s_m2 = (float*)(sm + SM_M2);
    float* s_h  = (float*)(sm + SM_H);
    const uint32_t mb = smem_u32(sm + SM_MBAR);

    if (t == 0) {
        mbar_init(mb + 0,  1);
        mbar_init(mb + 8,  1);
        mbar_init(mb + 16, 1);
        mbar_init(mb + 24, 1);
    }
    if (t < 64)      s_m2[t]     = g_m2[t];
    else if (t < 96) s_h[t - 64] = g_h[t - 64];
    __syncthreads();

    if (t == 0) {
        const uint32_t w3s = smem_u32(s_w3);
        const uint32_t cws = smem_u32(s_cw);
        // group 0: w3 rows 0..23
        mbar_expect_tx(mb + 0, 24 * 1024);
        for (int r = 0; r < 24; r++)
            bulk_cp(w3s + r * 1024, mix_w3 + r * N_WL + c0, 1024, mb + 0);
        // group 1: w3 rows 24..47
        mbar_expect_tx(mb + 8, 24 * 1024);
        for (int r = 24; r < 48; r++)
            bulk_cp(w3s + r * 1024, mix_w3 + r * N_WL + c0, 1024, mb + 8);
        // group 2: w3 rows 48..63 + cw2 rows 0..7
        mbar_expect_tx(mb + 16, 24 * 1024);
        for (int r = 48; r < 64; r++)
            bulk_cp(w3s + r * 1024, mix_w3 + r * N_WL + c0, 1024, mb + 16);
        for (int r = 0; r < 8; r++)
            bulk_cp(cws + r * 1024, cont_w2 + r * N_WL + c0, 1024, mb + 16);
        // group 3: cw2 rows 8..31 + biases
        mbar_expect_tx(mb + 24, 24 * 1024 + 2048);
        for (int r = 8; r < 32; r++)
            bulk_cp(cws + r * 1024, cont_w2 + r * N_WL + c0, 1024, mb + 24);
        bulk_cp(smem_u32(s_b3), mix_b3 + c0, 1024, mb + 24);
        bulk_cp(smem_u32(s_cb), cont_b2 + c0, 1024, mb + 24);
    }

    float am = 0.0f, ac = 0.0f;

    mbar_wait(mb + 0);
    #pragma unroll
    for (int r = 0; r < 24; r++)
        am = fmaf(s_m2[r], s_w3[r * 256 + t], am);

    mbar_wait(mb + 8);
    #pragma unroll
    for (int r = 24; r < 48; r++)
        am = fmaf(s_m2[r], s_w3[r * 256 + t], am);

    mbar_wait(mb + 16);
    #pragma unroll
    for (int r = 48; r < 64; r++)
        am = fmaf(s_m2[r], s_w3[r * 256 + t], am);
    #pragma unroll
    for (int r = 0; r < 8; r++)
        ac = fmaf(s_h[r], s_cw[r * 256 + t], ac);

    mbar_wait(mb + 24);
    #pragma unroll
    for (int r = 8; r < 32; r++)
        ac = fmaf(s_h[r], s_cw[r * 256 + t], ac);

    float zm = am + s_b3[t];
    float zc = ac + s_cb[t];

    // softplus(zc): 2 MUFU
    float e  = __expf(-fabsf(zc));
    float sp = fmaxf(zc, 0.0f) + __logf(1.0f + e);
    // cross * (1 + 0.1*(sigmoid(zm)-0.5)) == sp * (1 + 0.05*tanh(zm/2)): 1 MUFU
    float th = tanh_approx(zm * 0.5f);
    out[c0 + t] = sp * fmaf(0.05f, th, 1.0f);
}

// ---------------------------------------------------------------------------
extern "C" void kernel_launch(void* const* d_in, const int* in_sizes, int n_in,
                              void* d_out, int out_size)
{
    const float* wl      = (const float*)d_in[0];
    const float* T       = (const float*)d_in[1];
    const float* P       = (const float*)d_in[2];
    const float* o3      = (const float*)d_in[3];
    const float* h2o     = (const float*)d_in[4];
    const float* co2     = (const float*)d_in[5];
    const float* mix_w1  = (const float*)d_in[6];
    const float* mix_b1  = (const float*)d_in[7];
    const float* mix_w2  = (const float*)d_in[8];
    const float* mix_b2  = (const float*)d_in[9];
    const float* mix_w3  = (const float*)d_in[10];
    const float* mix_b3  = (const float*)d_in[11];
    const float* cont_w1 = (const float*)d_in[12];
    const float* cont_b1 = (const float*)d_in[13];
    const float* cont_w2 = (const float*)d_in[14];
    const float* cont_b2 = (const float*)d_in[15];
    float* out = (float*)d_out;

    static int smem_set = 0;
    if (!smem_set) {
        cudaFuncSetAttribute(main_kernel,
                             cudaFuncAttributeMaxDynamicSharedMemorySize, SMEM_TOTAL);
        smem_set = 1;
    }

    prep_kernel<<<1, 64>>>(wl, T, P, o3, h2o, co2,
                           mix_w1, mix_b1, mix_w2, mix_b2,
                           cont_w1, cont_b1, cont_w2, cont_b2);

    main_kernel<<<N_WL / 256, 256, SMEM_TOTAL>>>(mix_w3, mix_b3, cont_w2, cont_b2, out);
}

// round 9
// speedup vs baseline: 1.7625x; 1.7625x over previous
#include <cuda_runtime.h>
#include <cstdint>

#define N_WL 262144

// Persistent scratch (no allocations allowed)
__device__ float g_coef[96];   // [0:64) = m2, [64:96) = h

__device__ const float LNU0[10]  = {254.f, 280.f, 310.f, 940.f, 1130.f, 1380.f, 1400.f, 1600.f, 2000.f, 2700.f};
__device__ const float LSTR[10]  = {1.15e-17f, 5e-18f, 1.9e-19f, 2.5e-23f, 8.2e-24f, 1.8e-22f, 3.5e-25f, 7.8e-26f, 4.2e-24f, 1.2e-24f};
__device__ const float LWID[10]  = {2.0f, 3.0f, 2.5f, 3.0f, 2.5f, 4.0f, 3.0f, 2.5f, 4.0f, 3.5f};
__device__ const float LTE[10]   = {0.05f, 0.04f, 0.03f, 0.4f, 0.35f, 0.45f, 0.5f, 0.48f, 0.52f, 0.49f};
__device__ const float LMASS[10] = {48.f, 48.f, 48.f, 18.f, 18.f, 18.f, 44.f, 44.f, 44.f, 44.f};

// Voigt profile contribution for one line (prep kernel only).
__device__ __forceinline__ float voigt_line(float wl, float4 L) {
    float x  = (wl - L.x) * L.y;
    float y  = L.z;
    float ax = fabsf(x);
    float s  = ax + y;
    float w;
    if (s >= 15.0f) {
        float t2r = y * y - x * x;
        float t2i = -2.0f * x * y;
        float dr  = 0.5f + t2r;
        float di  = t2i;
        float nr  = 0.5641896f * y;
        float ni  = 0.5641896f * (-x);
        w = (nr * dr + ni * di) / (dr * dr + di * di);
    } else if (ax >= 5.5f) {
        float tr = y, ti = -x;
        float ur = y * y - x * x;
        float ui = -2.0f * x * y;
        float ar = 1.410474f + 0.5641896f * ur;
        float ai = 0.5641896f * ui;
        float nr = tr * ar - ti * ai;
        float ni = tr * ai + ti * ar;
        float u2r = ur * ur - ui * ui;
        float u2i = 2.0f * ur * ui;
        float dr = 0.75f + 3.0f * ur + u2r;
        float di = 3.0f * ui + u2i;
        w = (nr * dr + ni * di) / (dr * dr + di * di);
    } else {
        float xx = x * x;
        w = expf(-xx) * cosf(2.0f * x * y) * 0.5641896f
          + (2.0f * y / 3.14159265358979f) * sinf(xx) / (xx + y * y + 1e-10f);
    }
    return L.w * w;
}

__device__ __forceinline__ float softplus_f(float z) {
    return fmaxf(z, 0.0f) + log1pf(expf(-fabsf(z)));
}
__device__ __forceinline__ float silu_f(float z) {
    return z / (1.0f + expf(-z));
}
__device__ __forceinline__ float tanh_approx(float z) {
    float r;
    asm("tanh.approx.f32 %0, %1;" : "=f"(r) : "f"(z));
    return r;
}

__device__ __forceinline__ uint32_t smem_u32(const void* p) {
    uint32_t a;
    asm("{ .reg .u64 t; cvta.to.shared.u64 t, %1; cvt.u32.u64 %0, t; }" : "=r"(a) : "l"(p));
    return a;
}
__device__ __forceinline__ void cp_async16(uint32_t dst, const void* src) {
    asm volatile("cp.async.cg.shared.global [%0], [%1], 16;" :: "r"(dst), "l"(src) : "memory");
}

// ---------------------------------------------------------------------------
// Kernel A: tiny prep — h[32], cross[:8], m2[64] -> g_coef[96]
// ---------------------------------------------------------------------------
__global__ void prep_kernel(
    const float* __restrict__ wl,
    const float* __restrict__ Tp,  const float* __restrict__ Pp,
    const float* __restrict__ o3p, const float* __restrict__ h2op, const float* __restrict__ co2p,
    const float* __restrict__ mix_w1,  const float* __restrict__ mix_b1,
    const float* __restrict__ mix_w2,  const float* __restrict__ mix_b2,
    const float* __restrict__ cont_w1, const float* __restrict__ cont_b1,
    const float* __restrict__ cont_w2, const float* __restrict__ cont_b2)
{
    __shared__ float4 s_line[10];
    __shared__ float  s_h[32];
    __shared__ float  s_feat[10];
    __shared__ float  s_m1[64];

    const int t = threadIdx.x;   // 64 threads
    const float T = Tp[0];
    const float P = Pp[0];

    if (t < 10) {
        float conc = (t < 3) ? o3p[0] : ((t < 6) ? h2op[0] : co2p[0]);
        float nu0  = LNU0[t];
        float sT   = LSTR[t] * powf(273.15f / (T + 1e-12f), LTE[t]);
        float gL   = LWID[t] * (P / 101325.0f) * sqrtf(273.15f / (T + 1e-12f));
        float g    = 2.0f * 1.380649e-23f * T;
        g *= 6.02214076e23f;
        g /= (LMASS[t] + 1e-12f);
        float gD    = nu0 / 2.99792458e8f * sqrtf(g);
        float sigma = gD / 1.1774100226f;
        float inv_s = 1.0f / (sigma + 1e-12f);
        float y     = gL * inv_s;
        float amp   = conc * sT / (sigma * 1.7724538509f + 1e-12f);
        s_line[t] = make_float4(nu0, inv_s, y, amp);
    }
    if (t < 32) {
        float f0 = T / 273.15f;
        float f1 = P / 101325.0f;
        float f2 = h2op[0];
        float z = cont_b1[t]
                + f0 * cont_w1[t]
                + f1 * cont_w1[32 + t]
                + f2 * cont_w1[64 + t]
                +      cont_w1[96 + t];    // feat[3] = 1, feat[4] = 0
        float h = silu_f(z);
        s_h[t] = h;
        g_coef[64 + t] = h;
    }
    if (t == 0) {
        s_feat[0] = T / 273.15f;
        s_feat[1] = P / 101325.0f;
    }
    __syncthreads();

    if (t < 8) {
        float w = wl[t];
        float cross = 0.0f;
        #pragma unroll
        for (int l = 0; l < 10; l++) cross += voigt_line(w, s_line[l]);
        float z = cont_b2[t];
        #pragma unroll
        for (int j = 0; j < 32; j++) z += s_h[j] * cont_w2[j * N_WL + t];
        s_feat[2 + t] = cross + softplus_f(z);
    }
    __syncthreads();

    {
        float z = mix_b1[t];
        #pragma unroll
        for (int k = 0; k < 10; k++) z += s_feat[k] * mix_w1[k * 64 + t];
        s_m1[t] = silu_f(z);
    }
    __syncthreads();

    {
        float z = mix_b2[t];
        #pragma unroll
        for (int k = 0; k < 64; k++) z += s_m1[k] * mix_w2[k * 64 + t];
        g_coef[t] = silu_f(z);
    }
}

// ---------------------------------------------------------------------------
// Kernel B: cp.async (LDGSTS) double-buffered staging.
// 1024 CTAs x 256 threads, one column/thread. 96 rows in 8 stages of 12 rows;
// each stage 12KB staged via 3x16B cp.async/thread, consumed from smem.
// No destination registers -> outstanding copies unbounded by the RF.
// ---------------------------------------------------------------------------
#define ROWS_PER_STAGE 12
#define N_STAGES 8

__global__ void __launch_bounds__(256, 8) main_kernel(
    const float* __restrict__ mix_w3,  const float* __restrict__ mix_b3,
    const float* __restrict__ cont_w2, const float* __restrict__ cont_b2,
    float* __restrict__ out)
{
    __shared__ float buf[2][ROWS_PER_STAGE * 256];   // 2 x 12KB
    __shared__ float s_coef[96];

    const int t  = threadIdx.x;
    const int c0 = blockIdx.x * 256;

    if (t < 96) s_coef[t] = g_coef[t];

    // hoist bias loads (overlap with staging)
    float b3v = __ldg(mix_b3 + c0 + t);
    float cbv = __ldg(cont_b2 + c0 + t);

    auto issue_stage = [&](int s, int b) {
        const uint32_t base = smem_u32(&buf[b][0]);
        #pragma unroll
        for (int k = 0; k < 3; k++) {
            int idx = t + 256 * k;        // 0..767
            int ris = idx >> 6;           // row-in-stage 0..11
            int cg  = idx & 63;           // 16B group within the 1KB row chunk
            int r   = s * ROWS_PER_STAGE + ris;
            const float* src = (r < 64 ? mix_w3 + r * N_WL
                                       : cont_w2 + (r - 64) * N_WL) + c0 + cg * 4;
            cp_async16(base + (uint32_t)(ris * 1024 + cg * 16), src);
        }
        asm volatile("cp.async.commit_group;" ::: "memory");
    };

    issue_stage(0, 0);
    issue_stage(1, 1);

    float am = 0.0f, ac = 0.0f;

    #pragma unroll
    for (int s = 0; s < N_STAGES; s++) {
        if (s < N_STAGES - 1) asm volatile("cp.async.wait_group 1;" ::: "memory");
        else                  asm volatile("cp.async.wait_group 0;" ::: "memory");
        __syncthreads();      // all threads' copies for stage s visible

        const float* B = buf[s & 1];
        #pragma unroll
        for (int i = 0; i < ROWS_PER_STAGE; i++) {
            int r = s * ROWS_PER_STAGE + i;
            float v = B[i * 256 + t];
            float c = s_coef[r];
            if (r < 64) am = fmaf(c, v, am);
            else        ac = fmaf(c, v, ac);
        }
        __syncthreads();      // buffer s&1 fully consumed

        if (s + 2 < N_STAGES) issue_stage(s + 2, s & 1);
    }

    float zm = am + b3v;
    float zc = ac + cbv;

    // softplus(zc): 2 MUFU
    float e  = __expf(-fabsf(zc));
    float sp = fmaxf(zc, 0.0f) + __logf(1.0f + e);
    // cross * (1 + 0.1*(sigmoid(zm)-0.5)) == sp * (1 + 0.05*tanh(zm/2)): 1 MUFU
    float th = tanh_approx(zm * 0.5f);
    out[c0 + t] = sp * fmaf(0.05f, th, 1.0f);
}

// ---------------------------------------------------------------------------
extern "C" void kernel_launch(void* const* d_in, const int* in_sizes, int n_in,
                              void* d_out, int out_size)
{
    const float* wl      = (const float*)d_in[0];
    const float* T       = (const float*)d_in[1];
    const float* P       = (const float*)d_in[2];
    const float* o3      = (const float*)d_in[3];
    const float* h2o     = (const float*)d_in[4];
    const float* co2     = (const float*)d_in[5];
    const float* mix_w1  = (const float*)d_in[6];
    const float* mix_b1  = (const float*)d_in[7];
    const float* mix_w2  = (const float*)d_in[8];
    const float* mix_b2  = (const float*)d_in[9];
    const float* mix_w3  = (const float*)d_in[10];
    const float* mix_b3  = (const float*)d_in[11];
    const float* cont_w1 = (const float*)d_in[12];
    const float* cont_b1 = (const float*)d_in[13];
    const float* cont_w2 = (const float*)d_in[14];
    const float* cont_b2 = (const float*)d_in[15];
    float* out = (float*)d_out;

    prep_kernel<<<1, 64>>>(wl, T, P, o3, h2o, co2,
                           mix_w1, mix_b1, mix_w2, mix_b2,
                           cont_w1, cont_b1, cont_w2, cont_b2);

    main_kernel<<<N_WL / 256, 256>>>(mix_w3, mix_b3, cont_w2, cont_b2, out);
}

// round 10
// speedup vs baseline: 1.7650x; 1.0014x over previous
#include <cuda_runtime.h>
#include <cstdint>

#define N_WL 262144

// Persistent scratch (no allocations allowed)
__device__ float g_coef[96];   // [0:64) = m2, [64:96) = h

__device__ const float LNU0[10]  = {254.f, 280.f, 310.f, 940.f, 1130.f, 1380.f, 1400.f, 1600.f, 2000.f, 2700.f};
__device__ const float LSTR[10]  = {1.15e-17f, 5e-18f, 1.9e-19f, 2.5e-23f, 8.2e-24f, 1.8e-22f, 3.5e-25f, 7.8e-26f, 4.2e-24f, 1.2e-24f};
__device__ const float LWID[10]  = {2.0f, 3.0f, 2.5f, 3.0f, 2.5f, 4.0f, 3.0f, 2.5f, 4.0f, 3.5f};
__device__ const float LTE[10]   = {0.05f, 0.04f, 0.03f, 0.4f, 0.35f, 0.45f, 0.5f, 0.48f, 0.52f, 0.49f};
__device__ const float LMASS[10] = {48.f, 48.f, 48.f, 18.f, 18.f, 18.f, 44.f, 44.f, 44.f, 44.f};

// Voigt profile contribution for one line (prep kernel only).
__device__ __forceinline__ float voigt_line(float wl, float4 L) {
    float x  = (wl - L.x) * L.y;
    float y  = L.z;
    float ax = fabsf(x);
    float s  = ax + y;
    float w;
    if (s >= 15.0f) {
        float t2r = y * y - x * x;
        float t2i = -2.0f * x * y;
        float dr  = 0.5f + t2r;
        float di  = t2i;
        float nr  = 0.5641896f * y;
        float ni  = 0.5641896f * (-x);
        w = (nr * dr + ni * di) / (dr * dr + di * di);
    } else if (ax >= 5.5f) {
        float tr = y, ti = -x;
        float ur = y * y - x * x;
        float ui = -2.0f * x * y;
        float ar = 1.410474f + 0.5641896f * ur;
        float ai = 0.5641896f * ui;
        float nr = tr * ar - ti * ai;
        float ni = tr * ai + ti * ar;
        float u2r = ur * ur - ui * ui;
        float u2i = 2.0f * ur * ui;
        float dr = 0.75f + 3.0f * ur + u2r;
        float di = 3.0f * ui + u2i;
        w = (nr * dr + ni * di) / (dr * dr + di * di);
    } else {
        float xx = x * x;
        w = expf(-xx) * cosf(2.0f * x * y) * 0.5641896f
          + (2.0f * y / 3.14159265358979f) * sinf(xx) / (xx + y * y + 1e-10f);
    }
    return L.w * w;
}

__device__ __forceinline__ float softplus_f(float z) {
    return fmaxf(z, 0.0f) + log1pf(expf(-fabsf(z)));
}
__device__ __forceinline__ float silu_f(float z) {
    return z / (1.0f + expf(-z));
}
__device__ __forceinline__ float tanh_approx(float z) {
    float r;
    asm("tanh.approx.f32 %0, %1;" : "=f"(r) : "f"(z));
    return r;
}

__device__ __forceinline__ uint32_t smem_u32(const void* p) {
    uint32_t a;
    asm("{ .reg .u64 t; cvta.to.shared.u64 t, %1; cvt.u32.u64 %0, t; }" : "=r"(a) : "l"(p));
    return a;
}
__device__ __forceinline__ void cp_async16(uint32_t dst, const void* src) {
    asm volatile("cp.async.cg.shared.global [%0], [%1], 16;" :: "r"(dst), "l"(src) : "memory");
}

// ---------------------------------------------------------------------------
// Kernel A: tiny prep — h[32], cross[:8], m2[64] -> g_coef[96]
// ---------------------------------------------------------------------------
__global__ void prep_kernel(
    const float* __restrict__ wl,
    const float* __restrict__ Tp,  const float* __restrict__ Pp,
    const float* __restrict__ o3p, const float* __restrict__ h2op, const float* __restrict__ co2p,
    const float* __restrict__ mix_w1,  const float* __restrict__ mix_b1,
    const float* __restrict__ mix_w2,  const float* __restrict__ mix_b2,
    const float* __restrict__ cont_w1, const float* __restrict__ cont_b1,
    const float* __restrict__ cont_w2, const float* __restrict__ cont_b2)
{
    __shared__ float4 s_line[10];
    __shared__ float  s_h[32];
    __shared__ float  s_feat[10];
    __shared__ float  s_m1[64];

    const int t = threadIdx.x;   // 64 threads
    const float T = Tp[0];
    const float P = Pp[0];

    if (t < 10) {
        float conc = (t < 3) ? o3p[0] : ((t < 6) ? h2op[0] : co2p[0]);
        float nu0  = LNU0[t];
        float sT   = LSTR[t] * powf(273.15f / (T + 1e-12f), LTE[t]);
        float gL   = LWID[t] * (P / 101325.0f) * sqrtf(273.15f / (T + 1e-12f));
        float g    = 2.0f * 1.380649e-23f * T;
        g *= 6.02214076e23f;
        g /= (LMASS[t] + 1e-12f);
        float gD    = nu0 / 2.99792458e8f * sqrtf(g);
        float sigma = gD / 1.1774100226f;
        float inv_s = 1.0f / (sigma + 1e-12f);
        float y     = gL * inv_s;
        float amp   = conc * sT / (sigma * 1.7724538509f + 1e-12f);
        s_line[t] = make_float4(nu0, inv_s, y, amp);
    }
    if (t < 32) {
        float f0 = T / 273.15f;
        float f1 = P / 101325.0f;
        float f2 = h2op[0];
        float z = cont_b1[t]
                + f0 * cont_w1[t]
                + f1 * cont_w1[32 + t]
                + f2 * cont_w1[64 + t]
                +      cont_w1[96 + t];    // feat[3] = 1, feat[4] = 0
        float h = silu_f(z);
        s_h[t] = h;
        g_coef[64 + t] = h;
    }
    if (t == 0) {
        s_feat[0] = T / 273.15f;
        s_feat[1] = P / 101325.0f;
    }
    __syncthreads();

    if (t < 8) {
        float w = wl[t];
        float cross = 0.0f;
        #pragma unroll
        for (int l = 0; l < 10; l++) cross += voigt_line(w, s_line[l]);
        float z = cont_b2[t];
        #pragma unroll
        for (int j = 0; j < 32; j++) z += s_h[j] * cont_w2[j * N_WL + t];
        s_feat[2 + t] = cross + softplus_f(z);
    }
    __syncthreads();

    {
        float z = mix_b1[t];
        #pragma unroll
        for (int k = 0; k < 10; k++) z += s_feat[k] * mix_w1[k * 64 + t];
        s_m1[t] = silu_f(z);
    }
    __syncthreads();

    {
        float z = mix_b2[t];
        #pragma unroll
        for (int k = 0; k < 64; k++) z += s_m1[k] * mix_w2[k * 64 + t];
        g_coef[t] = silu_f(z);
    }
}

// ---------------------------------------------------------------------------
// Kernel B: cp.async with a DEEP 4-buffer ring.
// 12 stages x 8 rows (8KB/stage); wait_group 2 keeps 3 stages in flight;
// ONE __syncthreads per stage (doubles as the buffer-reuse guard: issuing
// stage s+3 writes buffer (s-1)%4, consumed at iteration s-1, and the
// iteration-s barrier orders that consumption before the new copies).
// ---------------------------------------------------------------------------
#define RPS 8          // rows per stage
#define NSTG 12        // stages
#define NBUF 4         // ring depth

__global__ void __launch_bounds__(256, 6) main_kernel(
    const float* __restrict__ mix_w3,  const float* __restrict__ mix_b3,
    const float* __restrict__ cont_w2, const float* __restrict__ cont_b2,
    float* __restrict__ out)
{
    __shared__ float buf[NBUF][RPS * 256];   // 4 x 8KB = 32KB
    __shared__ float s_coef[96];

    const int t  = threadIdx.x;
    const int c0 = blockIdx.x * 256;

    if (t < 96) s_coef[t] = g_coef[t];

    // bias loads overlap the staging pipeline
    float b3v = __ldg(mix_b3 + c0 + t);
    float cbv = __ldg(cont_b2 + c0 + t);

    auto issue_stage = [&](int s) {
        const uint32_t base = smem_u32(&buf[s & (NBUF - 1)][0]);
        #pragma unroll
        for (int k = 0; k < 2; k++) {
            int idx = t + 256 * k;        // 0..511
            int ris = idx >> 6;           // row-in-stage 0..7
            int cg  = idx & 63;           // 16B group within 1KB row chunk
            int r   = s * RPS + ris;
            const float* src = (r < 64 ? mix_w3 + r * N_WL
                                       : cont_w2 + (r - 64) * N_WL) + c0 + cg * 4;
            cp_async16(base + (uint32_t)(ris * 1024 + cg * 16), src);
        }
        asm volatile("cp.async.commit_group;" ::: "memory");
    };

    issue_stage(0);
    issue_stage(1);
    issue_stage(2);

    float am = 0.0f, ac = 0.0f;

    #pragma unroll
    for (int s = 0; s < NSTG; s++) {
        // ensure group s has landed (tail resolves at compile time)
        if (s < NSTG - 2)      asm volatile("cp.async.wait_group 2;" ::: "memory");
        else if (s == NSTG - 2) asm volatile("cp.async.wait_group 1;" ::: "memory");
        else                    asm volatile("cp.async.wait_group 0;" ::: "memory");
        __syncthreads();

        if (s + 3 < NSTG) issue_stage(s + 3);

        const float* B = buf[s & (NBUF - 1)];
        #pragma unroll
        for (int i = 0; i < RPS; i++) {
            int r = s * RPS + i;
            float v = B[i * 256 + t];
            float c = s_coef[r];
            if (r < 64) am = fmaf(c, v, am);
            else        ac = fmaf(c, v, ac);
        }
    }

    float zm = am + b3v;
    float zc = ac + cbv;

    // softplus(zc): 2 MUFU
    float e  = __expf(-fabsf(zc));
    float sp = fmaxf(zc, 0.0f) + __logf(1.0f + e);
    // cross * (1 + 0.1*(sigmoid(zm)-0.5)) == sp * (1 + 0.05*tanh(zm/2)): 1 MUFU
    float th = tanh_approx(zm * 0.5f);
    out[c0 + t] = sp * fmaf(0.05f, th, 1.0f);
}

// ---------------------------------------------------------------------------
extern "C" void kernel_launch(void* const* d_in, const int* in_sizes, int n_in,
                              void* d_out, int out_size)
{
    const float* wl      = (const float*)d_in[0];
    const float* T       = (const float*)d_in[1];
    const float* P       = (const float*)d_in[2];
    const float* o3      = (const float*)d_in[3];
    const float* h2o     = (const float*)d_in[4];
    const float* co2     = (const float*)d_in[5];
    const float* mix_w1  = (const float*)d_in[6];
    const float* mix_b1  = (const float*)d_in[7];
    const float* mix_w2  = (const float*)d_in[8];
    const float* mix_b2  = (const float*)d_in[9];
    const float* mix_w3  = (const float*)d_in[10];
    const float* mix_b3  = (const float*)d_in[11];
    const float* cont_w1 = (const float*)d_in[12];
    const float* cont_b1 = (const float*)d_in[13];
    const float* cont_w2 = (const float*)d_in[14];
    const float* cont_b2 = (const float*)d_in[15];
    float* out = (float*)d_out;

    prep_kernel<<<1, 64>>>(wl, T, P, o3, h2o, co2,
                           mix_w1, mix_b1, mix_w2, mix_b2,
                           cont_w1, cont_b1, cont_w2, cont_b2);

    main_kernel<<<N_WL / 256, 256>>>(mix_w3, mix_b3, cont_w2, cont_b2, out);
}

// round 11
// speedup vs baseline: 1.8000x; 1.0199x over previous
#include <cuda_runtime.h>
#include <cstdint>

#define N_WL 262144

// Persistent scratch (no allocations allowed)
__device__ float g_coef[96];   // [0:64) = m2, [64:96) = h

__device__ const float LNU0[10]  = {254.f, 280.f, 310.f, 940.f, 1130.f, 1380.f, 1400.f, 1600.f, 2000.f, 2700.f};
__device__ const float LSTR[10]  = {1.15e-17f, 5e-18f, 1.9e-19f, 2.5e-23f, 8.2e-24f, 1.8e-22f, 3.5e-25f, 7.8e-26f, 4.2e-24f, 1.2e-24f};
__device__ const float LWID[10]  = {2.0f, 3.0f, 2.5f, 3.0f, 2.5f, 4.0f, 3.0f, 2.5f, 4.0f, 3.5f};
__device__ const float LTE[10]   = {0.05f, 0.04f, 0.03f, 0.4f, 0.35f, 0.45f, 0.5f, 0.48f, 0.52f, 0.49f};
__device__ const float LMASS[10] = {48.f, 48.f, 48.f, 18.f, 18.f, 18.f, 44.f, 44.f, 44.f, 44.f};

// Voigt profile contribution for one line (prep kernel only).
__device__ __forceinline__ float voigt_line(float wl, float4 L) {
    float x  = (wl - L.x) * L.y;
    float y  = L.z;
    float ax = fabsf(x);
    float s  = ax + y;
    float w;
    if (s >= 15.0f) {
        float t2r = y * y - x * x;
        float t2i = -2.0f * x * y;
        float dr  = 0.5f + t2r;
        float di  = t2i;
        float nr  = 0.5641896f * y;
        float ni  = 0.5641896f * (-x);
        w = (nr * dr + ni * di) / (dr * dr + di * di);
    } else if (ax >= 5.5f) {
        float tr = y, ti = -x;
        float ur = y * y - x * x;
        float ui = -2.0f * x * y;
        float ar = 1.410474f + 0.5641896f * ur;
        float ai = 0.5641896f * ui;
        float nr = tr * ar - ti * ai;
        float ni = tr * ai + ti * ar;
        float u2r = ur * ur - ui * ui;
        float u2i = 2.0f * ur * ui;
        float dr = 0.75f + 3.0f * ur + u2r;
        float di = 3.0f * ui + u2i;
        w = (nr * dr + ni * di) / (dr * dr + di * di);
    } else {
        float xx = x * x;
        w = expf(-xx) * cosf(2.0f * x * y) * 0.5641896f
          + (2.0f * y / 3.14159265358979f) * sinf(xx) / (xx + y * y + 1e-10f);
    }
    return L.w * w;
}

__device__ __forceinline__ float softplus_f(float z) {
    return fmaxf(z, 0.0f) + log1pf(expf(-fabsf(z)));
}
__device__ __forceinline__ float silu_f(float z) {
    return z / (1.0f + expf(-z));
}
__device__ __forceinline__ float tanh_approx(float z) {
    float r;
    asm("tanh.approx.f32 %0, %1;" : "=f"(r) : "f"(z));
    return r;
}

__device__ __forceinline__ uint32_t smem_u32(const void* p) {
    uint32_t a;
    asm("{ .reg .u64 t; cvta.to.shared.u64 t, %1; cvt.u32.u64 %0, t; }" : "=r"(a) : "l"(p));
    return a;
}
__device__ __forceinline__ void cp_async16(uint32_t dst, const void* src) {
    asm volatile("cp.async.cg.shared.global [%0], [%1], 16;" :: "r"(dst), "l"(src) : "memory");
}

// ---------------------------------------------------------------------------
// Kernel A: tiny prep — h[32], cross[:8], m2[64] -> g_coef[96]
// ---------------------------------------------------------------------------
__global__ void prep_kernel(
    const float* __restrict__ wl,
    const float* __restrict__ Tp,  const float* __restrict__ Pp,
    const float* __restrict__ o3p, const float* __restrict__ h2op, const float* __restrict__ co2p,
    const float* __restrict__ mix_w1,  const float* __restrict__ mix_b1,
    const float* __restrict__ mix_w2,  const float* __restrict__ mix_b2,
    const float* __restrict__ cont_w1, const float* __restrict__ cont_b1,
    const float* __restrict__ cont_w2, const float* __restrict__ cont_b2)
{
    __shared__ float4 s_line[10];
    __shared__ float  s_h[32];
    __shared__ float  s_feat[10];
    __shared__ float  s_m1[64];

    const int t = threadIdx.x;   // 64 threads
    const float T = Tp[0];
    const float P = Pp[0];

    if (t < 10) {
        float conc = (t < 3) ? o3p[0] : ((t < 6) ? h2op[0] : co2p[0]);
        float nu0  = LNU0[t];
        float sT   = LSTR[t] * powf(273.15f / (T + 1e-12f), LTE[t]);
        float gL   = LWID[t] * (P / 101325.0f) * sqrtf(273.15f / (T + 1e-12f));
        float g    = 2.0f * 1.380649e-23f * T;
        g *= 6.02214076e23f;
        g /= (LMASS[t] + 1e-12f);
        float gD    = nu0 / 2.99792458e8f * sqrtf(g);
        float sigma = gD / 1.1774100226f;
        float inv_s = 1.0f / (sigma + 1e-12f);
        float y     = gL * inv_s;
        float amp   = conc * sT / (sigma * 1.7724538509f + 1e-12f);
        s_line[t] = make_float4(nu0, inv_s, y, amp);
    }
    if (t < 32) {
        float f0 = T / 273.15f;
        float f1 = P / 101325.0f;
        float f2 = h2op[0];
        float z = cont_b1[t]
                + f0 * cont_w1[t]
                + f1 * cont_w1[32 + t]
                + f2 * cont_w1[64 + t]
                +      cont_w1[96 + t];    // feat[3] = 1, feat[4] = 0
        float h = silu_f(z);
        s_h[t] = h;
        g_coef[64 + t] = h;
    }
    if (t == 0) {
        s_feat[0] = T / 273.15f;
        s_feat[1] = P / 101325.0f;
    }
    __syncthreads();

    if (t < 8) {
        float w = wl[t];
        float cross = 0.0f;
        #pragma unroll
        for (int l = 0; l < 10; l++) cross += voigt_line(w, s_line[l]);
        float z = cont_b2[t];
        #pragma unroll
        for (int j = 0; j < 32; j++) z += s_h[j] * cont_w2[j * N_WL + t];
        s_feat[2 + t] = cross + softplus_f(z);
    }
    __syncthreads();

    {
        float z = mix_b1[t];
        #pragma unroll
        for (int k = 0; k < 10; k++) z += s_feat[k] * mix_w1[k * 64 + t];
        s_m1[t] = silu_f(z);
    }
    __syncthreads();

    {
        float z = mix_b2[t];
        #pragma unroll
        for (int k = 0; k < 64; k++) z += s_m1[k] * mix_w2[k * 64 + t];
        g_coef[t] = silu_f(z);
    }
}

// ---------------------------------------------------------------------------
// Kernel B: cp.async (LDGSTS) double-buffered staging (R9 config — best main).
// PDL: launched with programmatic stream serialization, so blocks start while
// prep is still running; the first two copy stages + bias loads are issued
// before cudaGridDependencySynchronize(), overlapping prep entirely.
// ---------------------------------------------------------------------------
#define ROWS_PER_STAGE 12
#define N_STAGES 8

__global__ void __launch_bounds__(256, 8) main_kernel(
    const float* __restrict__ mix_w3,  const float* __restrict__ mix_b3,
    const float* __restrict__ cont_w2, const float* __restrict__ cont_b2,
    float* __restrict__ out)
{
    __shared__ float buf[2][ROWS_PER_STAGE * 256];   // 2 x 12KB
    __shared__ float s_coef[96];

    const int t  = threadIdx.x;
    const int c0 = blockIdx.x * 256;

    auto issue_stage = [&](int s, int b) {
        const uint32_t base = smem_u32(&buf[b][0]);
        #pragma unroll
        for (int k = 0; k < 3; k++) {
            int idx = t + 256 * k;        // 0..767
            int ris = idx >> 6;           // row-in-stage 0..11
            int cg  = idx & 63;           // 16B group within the 1KB row chunk
            int r   = s * ROWS_PER_STAGE + ris;
            const float* src = (r < 64 ? mix_w3 + r * N_WL
                                       : cont_w2 + (r - 64) * N_WL) + c0 + cg * 4;
            cp_async16(base + (uint32_t)(ris * 1024 + cg * 16), src);
        }
        asm volatile("cp.async.commit_group;" ::: "memory");
    };

    // Everything here is independent of prep's output: start the memory
    // pipeline immediately (possibly while prep is still executing).
    issue_stage(0, 0);
    issue_stage(1, 1);
    float b3v = __ldg(mix_b3 + c0 + t);
    float cbv = __ldg(cont_b2 + c0 + t);

    // Now wait for prep's g_coef writes to be visible.
    cudaGridDependencySynchronize();
    if (t < 96) s_coef[t] = g_coef[t];

    float am = 0.0f, ac = 0.0f;

    #pragma unroll
    for (int s = 0; s < N_STAGES; s++) {
        if (s < N_STAGES - 1) asm volatile("cp.async.wait_group 1;" ::: "memory");
        else                  asm volatile("cp.async.wait_group 0;" ::: "memory");
        __syncthreads();      // all threads' copies for stage s visible (+ s_coef)

        const float* B = buf[s & 1];
        #pragma unroll
        for (int i = 0; i < ROWS_PER_STAGE; i++) {
            int r = s * ROWS_PER_STAGE + i;
            float v = B[i * 256 + t];
            float c = s_coef[r];
            if (r < 64) am = fmaf(c, v, am);
            else        ac = fmaf(c, v, ac);
        }
        __syncthreads();      // buffer s&1 fully consumed

        if (s + 2 < N_STAGES) issue_stage(s + 2, s & 1);
    }

    float zm = am + b3v;
    float zc = ac + cbv;

    // softplus(zc): 2 MUFU
    float e  = __expf(-fabsf(zc));
    float sp = fmaxf(zc, 0.0f) + __logf(1.0f + e);
    // cross * (1 + 0.1*(sigmoid(zm)-0.5)) == sp * (1 + 0.05*tanh(zm/2)): 1 MUFU
    float th = tanh_approx(zm * 0.5f);
    out[c0 + t] = sp * fmaf(0.05f, th, 1.0f);
}

// ---------------------------------------------------------------------------
extern "C" void kernel_launch(void* const* d_in, const int* in_sizes, int n_in,
                              void* d_out, int out_size)
{
    const float* wl      = (const float*)d_in[0];
    const float* T       = (const float*)d_in[1];
    const float* P       = (const float*)d_in[2];
    const float* o3      = (const float*)d_in[3];
    const float* h2o     = (const float*)d_in[4];
    const float* co2     = (const float*)d_in[5];
    const float* mix_w1  = (const float*)d_in[6];
    const float* mix_b1  = (const float*)d_in[7];
    const float* mix_w2  = (const float*)d_in[8];
    const float* mix_b2  = (const float*)d_in[9];
    const float* mix_w3  = (const float*)d_in[10];
    const float* mix_b3  = (const float*)d_in[11];
    const float* cont_w1 = (const float*)d_in[12];
    const float* cont_b1 = (const float*)d_in[13];
    const float* cont_w2 = (const float*)d_in[14];
    const float* cont_b2 = (const float*)d_in[15];
    float* out = (float*)d_out;

    prep_kernel<<<1, 64>>>(wl, T, P, o3, h2o, co2,
                           mix_w1, mix_b1, mix_w2, mix_b2,
                           cont_w1, cont_b1, cont_w2, cont_b2);

    // PDL launch: main may begin before prep completes; device code holds the
    // dependency via cudaGridDependencySynchronize().
    cudaLaunchConfig_t cfg = {};
    cfg.gridDim  = dim3(N_WL / 256);
    cfg.blockDim = dim3(256);
    cfg.dynamicSmemBytes = 0;
    cfg.stream = 0;
    cudaLaunchAttribute attrs[1];
    attrs[0].id = cudaLaunchAttributeProgrammaticStreamSerialization;
    attrs[0].val.programmaticStreamSerializationAllowed = 1;
    cfg.attrs = attrs;
    cfg.numAttrs = 1;
    cudaLaunchKernelEx(&cfg, main_kernel, mix_w3, mix_b3, cont_w2, cont_b2, out);
}